// round 10
// baseline (speedup 1.0000x reference)
#include <cuda_runtime.h>
#include <cuda_bf16.h>
#include <cuda_fp16.h>
#include <cstdint>

#define N_NODES 50000
#define N_EDGES 800000
#define F_IN    128
#define HDIM    128
#define N_HEADS 8
#define HID     16
#define F_OUT   32
#define NEG_SLOPE 0.2f

// ---------------- device scratch ----------------
__device__ __half g_z1[N_NODES * HDIM];
__device__ float  g_es1[N_NODES * N_HEADS];
__device__ float  g_ed1[N_NODES * N_HEADS];
__device__ float  g_h1[N_NODES * HDIM];
__device__ __half g_z2[N_NODES * F_OUT];
__device__ float  g_es2[N_NODES];
__device__ float  g_ed2[N_NODES];
__device__ int    g_deg[N_NODES];
__device__ int    g_rowptr[N_NODES + 1];
__device__ int    g_cursor[N_NODES];
__device__ int    g_csrsrc[N_EDGES];
__device__ int    g_bsum[64];

// ---------------- CSR build ----------------
__global__ void k_hist(const int* __restrict__ dst) {
    int e = blockIdx.x * 256 + threadIdx.x;
    if (e < N_EDGES) atomicAdd(&g_deg[dst[e]], 1);
}

#define SCAN_TPB 256
#define SCAN_ITEMS 8
#define SCAN_TILE 2048
#define SCAN_NTILES ((N_NODES + SCAN_TILE - 1) / SCAN_TILE)   // 25

__global__ void __launch_bounds__(SCAN_TPB) k_scan1() {
    __shared__ int warpsum[8];
    const int t = threadIdx.x;
    const int lane = t & 31, wid = t >> 5;
    const int base = blockIdx.x * SCAN_TILE + t * SCAN_ITEMS;
    int v[SCAN_ITEMS];
    int s = 0;
#pragma unroll
    for (int i = 0; i < SCAN_ITEMS; i++) {
        int idx = base + i;
        v[i] = (idx < N_NODES) ? g_deg[idx] : 0;
        s += v[i];
    }
    int ps = s;
#pragma unroll
    for (int off = 1; off < 32; off <<= 1) {
        int nv = __shfl_up_sync(0xffffffffu, ps, off);
        if (lane >= off) ps += nv;
    }
    if (lane == 31) warpsum[wid] = ps;
    __syncthreads();
    if (wid == 0) {
        int ws = (lane < 8) ? warpsum[lane] : 0;
#pragma unroll
        for (int off = 1; off < 8; off <<= 1) {
            int nv = __shfl_up_sync(0xffffffffu, ws, off);
            if (lane >= off) ws += nv;
        }
        if (lane < 8) warpsum[lane] = ws;
    }
    __syncthreads();
    int excl = ps - s + (wid ? warpsum[wid - 1] : 0);
    int run = excl;
#pragma unroll
    for (int i = 0; i < SCAN_ITEMS; i++) {
        int idx = base + i;
        if (idx < N_NODES) g_rowptr[idx] = run;
        run += v[i];
    }
    if (t == SCAN_TPB - 1) g_bsum[blockIdx.x] = run;
}

__global__ void __launch_bounds__(SCAN_TPB) k_scan2() {
    const int t = threadIdx.x;
    const int lane = t & 31;
    const int b = blockIdx.x;
    int v = (lane < b) ? g_bsum[lane] : 0;
#pragma unroll
    for (int off = 16; off; off >>= 1) v += __shfl_xor_sync(0xffffffffu, v, off);
    const int offn = v;
    const int base = b * SCAN_TILE + t * SCAN_ITEMS;
#pragma unroll
    for (int i = 0; i < SCAN_ITEMS; i++) {
        int idx = base + i;
        if (idx < N_NODES) {
            int r = g_rowptr[idx] + offn;
            g_rowptr[idx] = r;
            g_cursor[idx] = r;
        }
    }
    if (b == 0 && t == 0) g_rowptr[N_NODES] = N_EDGES;
}

__global__ void k_scatter(const int* __restrict__ src, const int* __restrict__ dst) {
    int e = blockIdx.x * 256 + threadIdx.x;
    if (e < N_EDGES) {
        int p = atomicAdd(&g_cursor[dst[e]], 1);
        g_csrsrc[p] = src[e];
    }
}

// ---------------- bf16 split-MMA GEMM + fused attention-dot epilogue ----------------
__device__ __forceinline__ void ldsm_x4(uint32_t& r0, uint32_t& r1, uint32_t& r2, uint32_t& r3,
                                        uint32_t addr) {
    asm volatile("ldmatrix.sync.aligned.m8n8.x4.shared.b16 {%0,%1,%2,%3}, [%4];"
                 : "=r"(r0), "=r"(r1), "=r"(r2), "=r"(r3) : "r"(addr));
}
__device__ __forceinline__ void ldsm_x4t(uint32_t& r0, uint32_t& r1, uint32_t& r2, uint32_t& r3,
                                         uint32_t addr) {
    asm volatile("ldmatrix.sync.aligned.m8n8.x4.trans.shared.b16 {%0,%1,%2,%3}, [%4];"
                 : "=r"(r0), "=r"(r1), "=r"(r2), "=r"(r3) : "r"(addr));
}
__device__ __forceinline__ void mma_bf16(float* c, const uint32_t* a, uint32_t b0, uint32_t b1) {
    asm volatile(
        "mma.sync.aligned.m16n8k16.row.col.f32.bf16.bf16.f32 "
        "{%0,%1,%2,%3}, {%4,%5,%6,%7}, {%8,%9}, {%0,%1,%2,%3};"
        : "+f"(c[0]), "+f"(c[1]), "+f"(c[2]), "+f"(c[3])
        : "r"(a[0]), "r"(a[1]), "r"(a[2]), "r"(a[3]), "r"(b0), "r"(b1));
}
__device__ __forceinline__ void cvt_hilo(float x, __nv_bfloat16& h, __nv_bfloat16& l) {
    h = __float2bfloat16(x);
    l = __float2bfloat16(x - __bfloat162float(h));
}

template <int BN, int NWARP, int WC, int NH, int MINB, typename CT>
__global__ void __launch_bounds__(NWARP * 32, MINB)
k_gemm_tc(const float* __restrict__ A, const float* __restrict__ B,
          CT* __restrict__ C,
          const float* __restrict__ avs, const float* __restrict__ avd,
          float* __restrict__ esp, float* __restrict__ edp, int M) {
    constexpr int BM = 128, K = 128, BK = 16, NK = K / BK;
    constexpr int NT = NWARP * 32;
    constexpr int SAS = 24;
    constexpr int BNS = BN + 8;
    constexpr int WR = NWARP / WC;
    constexpr int WTN = BN / WC;
    constexpr int NTW = WTN / 8;
    constexpr int HD = BN / NH;
    constexpr int HWN = WTN / HD;
    constexpr int LA4 = (BM * BK / 4) / NT;
    constexpr int LB4 = (BK * BN / 4) / NT;

    __shared__ __nv_bfloat16 sAh[2][BM][SAS];
    __shared__ __nv_bfloat16 sAl[2][BM][SAS];
    __shared__ __nv_bfloat16 sBh[2][BK][BNS];
    __shared__ __nv_bfloat16 sBl[2][BK][BNS];

    const int tid = threadIdx.x;
    const int lane = tid & 31;
    const int wid = tid >> 5;
    const int row0 = blockIdx.x * BM;
    const int tmW = (wid / WC) * (BM / WR);
    const int tnW = (wid % WC) * WTN;

    float4 ra[LA4], rb[LB4];

    auto ldg_tile = [&](int kt) {
        const int k0 = kt * BK;
#pragma unroll
        for (int l = 0; l < LA4; l++) {
            int idx = tid + l * NT;
            int r = idx >> 2, kq = idx & 3;
            int row = row0 + r;
            ra[l] = (row < M) ? *(const float4*)&A[(size_t)row * K + k0 + kq * 4]
                              : make_float4(0.f, 0.f, 0.f, 0.f);
        }
#pragma unroll
        for (int l = 0; l < LB4; l++) {
            int idx = tid + l * NT;
            int k = idx / (BN / 4), nq = idx % (BN / 4);
            rb[l] = *(const float4*)&B[(size_t)(k0 + k) * BN + nq * 4];
        }
    };
    auto sts_tile = [&](int buf) {
#pragma unroll
        for (int l = 0; l < LA4; l++) {
            int idx = tid + l * NT;
            int r = idx >> 2, kq = idx & 3;
            __nv_bfloat16 h0, h1, h2, h3, l0, l1, l2, l3;
            cvt_hilo(ra[l].x, h0, l0); cvt_hilo(ra[l].y, h1, l1);
            cvt_hilo(ra[l].z, h2, l2); cvt_hilo(ra[l].w, h3, l3);
            *(__nv_bfloat162*)&sAh[buf][r][kq * 4]     = __nv_bfloat162(h0, h1);
            *(__nv_bfloat162*)&sAh[buf][r][kq * 4 + 2] = __nv_bfloat162(h2, h3);
            *(__nv_bfloat162*)&sAl[buf][r][kq * 4]     = __nv_bfloat162(l0, l1);
            *(__nv_bfloat162*)&sAl[buf][r][kq * 4 + 2] = __nv_bfloat162(l2, l3);
        }
#pragma unroll
        for (int l = 0; l < LB4; l++) {
            int idx = tid + l * NT;
            int k = idx / (BN / 4), nq = idx % (BN / 4);
            __nv_bfloat16 h0, h1, h2, h3, l0, l1, l2, l3;
            cvt_hilo(rb[l].x, h0, l0); cvt_hilo(rb[l].y, h1, l1);
            cvt_hilo(rb[l].z, h2, l2); cvt_hilo(rb[l].w, h3, l3);
            *(__nv_bfloat162*)&sBh[buf][k][nq * 4]     = __nv_bfloat162(h0, h1);
            *(__nv_bfloat162*)&sBh[buf][k][nq * 4 + 2] = __nv_bfloat162(h2, h3);
            *(__nv_bfloat162*)&sBl[buf][k][nq * 4]     = __nv_bfloat162(l0, l1);
            *(__nv_bfloat162*)&sBl[buf][k][nq * 4 + 2] = __nv_bfloat162(l2, l3);
        }
    };

    float acc[2][NTW][4];
#pragma unroll
    for (int i = 0; i < 2; i++)
#pragma unroll
        for (int j = 0; j < NTW; j++)
#pragma unroll
            for (int q = 0; q < 4; q++) acc[i][j][q] = 0.f;

    ldg_tile(0);
    sts_tile(0);
    int cur = 0;

    const int aRow = (lane & 7) + ((lane & 8) ? 8 : 0);
    const int aCol = (lane & 16) ? 8 : 0;
    const int bK = aRow;
    const int bN = aCol;

    for (int kt = 0; kt < NK; kt++) {
        if (kt + 1 < NK) ldg_tile(kt + 1);
        __syncthreads();

        uint32_t ah[2][4], al[2][4];
#pragma unroll
        for (int mt = 0; mt < 2; mt++) {
            int r = tmW + mt * 16 + aRow;
            uint32_t addrh = (uint32_t)__cvta_generic_to_shared(&sAh[cur][r][aCol]);
            uint32_t addrl = (uint32_t)__cvta_generic_to_shared(&sAl[cur][r][aCol]);
            ldsm_x4(ah[mt][0], ah[mt][1], ah[mt][2], ah[mt][3], addrh);
            ldsm_x4(al[mt][0], al[mt][1], al[mt][2], al[mt][3], addrl);
        }
#pragma unroll
        for (int p = 0; p < NTW / 2; p++) {
            int n = tnW + p * 16 + bN;
            uint32_t addrh = (uint32_t)__cvta_generic_to_shared(&sBh[cur][bK][n]);
            uint32_t addrl = (uint32_t)__cvta_generic_to_shared(&sBl[cur][bK][n]);
            uint32_t bh0, bh1, bh2, bh3, bl0, bl1, bl2, bl3;
            ldsm_x4t(bh0, bh1, bh2, bh3, addrh);
            ldsm_x4t(bl0, bl1, bl2, bl3, addrl);
#pragma unroll
            for (int mt = 0; mt < 2; mt++) {
                mma_bf16(acc[mt][2 * p],     ah[mt], bh0, bh1);
                mma_bf16(acc[mt][2 * p],     ah[mt], bl0, bl1);
                mma_bf16(acc[mt][2 * p],     al[mt], bh0, bh1);
                mma_bf16(acc[mt][2 * p + 1], ah[mt], bh2, bh3);
                mma_bf16(acc[mt][2 * p + 1], ah[mt], bl2, bl3);
                mma_bf16(acc[mt][2 * p + 1], al[mt], bh2, bh3);
            }
        }
        if (kt + 1 < NK) sts_tile(cur ^ 1);
        cur ^= 1;
    }

    const int cRow = lane >> 2;
    const int cCol = (lane & 3) * 2;
#pragma unroll
    for (int mt = 0; mt < 2; mt++)
#pragma unroll
        for (int nt = 0; nt < NTW; nt++) {
            int col = tnW + nt * 8 + cCol;
            int r1 = row0 + tmW + mt * 16 + cRow;
            int r2 = r1 + 8;
            if constexpr (sizeof(CT) == 2) {
                if (r1 < M) *(__half2*)&C[(size_t)r1 * BN + col] =
                    __floats2half2_rn(acc[mt][nt][0], acc[mt][nt][1]);
                if (r2 < M) *(__half2*)&C[(size_t)r2 * BN + col] =
                    __floats2half2_rn(acc[mt][nt][2], acc[mt][nt][3]);
            } else {
                if (r1 < M) *(float2*)&C[(size_t)r1 * BN + col] = make_float2(acc[mt][nt][0], acc[mt][nt][1]);
                if (r2 < M) *(float2*)&C[(size_t)r2 * BN + col] = make_float2(acc[mt][nt][2], acc[mt][nt][3]);
            }
        }

    float pes[2][2][HWN], ped[2][2][HWN];
#pragma unroll
    for (int mt = 0; mt < 2; mt++)
#pragma unroll
        for (int pr = 0; pr < 2; pr++)
#pragma unroll
            for (int hw = 0; hw < HWN; hw++) { pes[mt][pr][hw] = 0.f; ped[mt][pr][hw] = 0.f; }
#pragma unroll
    for (int mt = 0; mt < 2; mt++)
#pragma unroll
        for (int nt = 0; nt < NTW; nt++) {
            int hw = (nt * 8) / HD;
            int c = tnW + nt * 8 + cCol;
            float s0 = avs[c], s1 = avs[c + 1];
            float d0 = avd[c], d1 = avd[c + 1];
            pes[mt][0][hw] += acc[mt][nt][0] * s0 + acc[mt][nt][1] * s1;
            pes[mt][1][hw] += acc[mt][nt][2] * s0 + acc[mt][nt][3] * s1;
            ped[mt][0][hw] += acc[mt][nt][0] * d0 + acc[mt][nt][1] * d1;
            ped[mt][1][hw] += acc[mt][nt][2] * d0 + acc[mt][nt][3] * d1;
        }
#pragma unroll
    for (int mt = 0; mt < 2; mt++)
#pragma unroll
        for (int pr = 0; pr < 2; pr++)
#pragma unroll
            for (int hw = 0; hw < HWN; hw++) {
#pragma unroll
                for (int off = 1; off <= 2; off <<= 1) {
                    pes[mt][pr][hw] += __shfl_xor_sync(0xffffffffu, pes[mt][pr][hw], off);
                    ped[mt][pr][hw] += __shfl_xor_sync(0xffffffffu, ped[mt][pr][hw], off);
                }
            }
    if ((lane & 3) == 0) {
#pragma unroll
        for (int mt = 0; mt < 2; mt++)
#pragma unroll
            for (int pr = 0; pr < 2; pr++) {
                int row = row0 + tmW + mt * 16 + pr * 8 + cRow;
                if (row < M) {
#pragma unroll
                    for (int hw = 0; hw < HWN; hw++) {
                        int hg = tnW / HD + hw;
                        esp[(size_t)row * NH + hg] = pes[mt][pr][hw];
                        edp[(size_t)row * NH + hg] = ped[mt][pr][hw];
                    }
                }
            }
    }
}

// ---------------- layer1 aggregation (warp/node, unroll-8 gather) ----------------
__global__ void __launch_bounds__(256) k_agg1() {
    __shared__ int   ss[8][32];
    __shared__ float ws[8][8][33];
    const int w = threadIdx.x >> 5;
    const int lane = threadIdx.x & 31;
    const int n = blockIdx.x * 8 + w;
    if (n >= N_NODES) return;
    const int beg = g_rowptr[n], end = g_rowptr[n + 1];
    const int head = lane >> 2;

    float ed[8];
    {
        float4 lo = *(const float4*)&g_ed1[n * 8];
        float4 hi = *(const float4*)&g_ed1[n * 8 + 4];
        ed[0] = lo.x; ed[1] = lo.y; ed[2] = lo.z; ed[3] = lo.w;
        ed[4] = hi.x; ed[5] = hi.y; ed[6] = hi.z; ed[7] = hi.w;
    }

    float4 acc = make_float4(0.f, 0.f, 0.f, 0.f);
    float ssum[8];
#pragma unroll
    for (int h = 0; h < 8; h++) ssum[h] = 0.f;

    for (int base = beg; base < end; base += 32) {
        const int cnt = min(32, end - base);
        float wv[8];
        int sv = 0;
        if (lane < cnt) {
            sv = g_csrsrc[base + lane];
            float4 lo = *(const float4*)&g_es1[sv * 8];
            float4 hi = *(const float4*)&g_es1[sv * 8 + 4];
            float es[8] = {lo.x, lo.y, lo.z, lo.w, hi.x, hi.y, hi.z, hi.w};
#pragma unroll
            for (int h = 0; h < 8; h++) {
                float t = es[h] + ed[h];
                t = (t >= 0.f) ? t : NEG_SLOPE * t;
                wv[h] = __expf(t);
                ssum[h] += wv[h];
            }
        } else {
#pragma unroll
            for (int h = 0; h < 8; h++) wv[h] = 0.f;
        }
        ss[w][lane] = sv;
#pragma unroll
        for (int h = 0; h < 8; h++) ws[w][h][lane] = wv[h];
        __syncwarp();

        // branch-free unroll-8: entries beyond cnt have wt=0, sv=0 (harmless hot-row gather)
        for (int j = 0; j < cnt; j += 8) {
#pragma unroll
            for (int u = 0; u < 8; u++) {
                int s = ss[w][j + u];
                float wt = ws[w][head][j + u];
                uint2 raw = *(const uint2*)&g_z1[(size_t)s * HDIM + lane * 4];
                float2 f0 = __half22float2(*(__half2*)&raw.x);
                float2 f1 = __half22float2(*(__half2*)&raw.y);
                acc.x += wt * f0.x; acc.y += wt * f0.y;
                acc.z += wt * f1.x; acc.w += wt * f1.y;
            }
        }
        __syncwarp();
    }

#pragma unroll
    for (int h = 0; h < 8; h++)
#pragma unroll
        for (int off = 16; off; off >>= 1)
            ssum[h] += __shfl_xor_sync(0xffffffffu, ssum[h], off);

    float4 r = make_float4(0.f, 0.f, 0.f, 0.f);
    if (end > beg) {
        float inv = 1.f / ssum[head];
        r.x = acc.x * inv; r.y = acc.y * inv;
        r.z = acc.z * inv; r.w = acc.w * inv;
    }
    r.x = (r.x > 0.f) ? r.x : expm1f(r.x);
    r.y = (r.y > 0.f) ? r.y : expm1f(r.y);
    r.z = (r.z > 0.f) ? r.z : expm1f(r.z);
    r.w = (r.w > 0.f) ? r.w : expm1f(r.w);
    *(float4*)&g_h1[(size_t)n * HDIM + lane * 4] = r;
}

// ---------------- layer2 aggregation (warp/node, 8 edges in flight) ----------------
__global__ void __launch_bounds__(256) k_agg2(float* __restrict__ out) {
    __shared__ int   ss[8][32];
    __shared__ float ws[8][32];
    const int w = threadIdx.x >> 5;
    const int lane = threadIdx.x & 31;
    const int n = blockIdx.x * 8 + w;
    if (n >= N_NODES) return;
    const int beg = g_rowptr[n], end = g_rowptr[n + 1];
    const float ed = g_ed2[n];
    const int eslot = lane >> 3;
    const int cg = lane & 7;
    float4 acc = make_float4(0.f, 0.f, 0.f, 0.f);
    float S = 0.f;

    for (int base = beg; base < end; base += 32) {
        const int cnt = min(32, end - base);
        float wv = 0.f;
        int sv = 0;
        if (lane < cnt) {
            sv = g_csrsrc[base + lane];
            float t = g_es2[sv] + ed;
            t = (t >= 0.f) ? t : NEG_SLOPE * t;
            wv = __expf(t);
            S += wv;
        }
        ss[w][lane] = sv;
        ws[w][lane] = wv;
        __syncwarp();

        // 8 edges in flight: two batched gathers per iteration
        for (int j = 0; j < cnt; j += 8) {
            int j1 = j + eslot;          // <= 27+4 = 31
            int j2 = j + 4 + eslot;      // <= 31
            int s1v = ss[w][j1];
            int s2v = ss[w][j2];
            float w1 = ws[w][j1];
            float w2 = ws[w][j2];
            uint2 raw1 = *(const uint2*)&g_z2[(size_t)s1v * F_OUT + cg * 4];
            uint2 raw2 = *(const uint2*)&g_z2[(size_t)s2v * F_OUT + cg * 4];
            float2 a0 = __half22float2(*(__half2*)&raw1.x);
            float2 a1 = __half22float2(*(__half2*)&raw1.y);
            float2 b0 = __half22float2(*(__half2*)&raw2.x);
            float2 b1 = __half22float2(*(__half2*)&raw2.y);
            acc.x += w1 * a0.x + w2 * b0.x;
            acc.y += w1 * a0.y + w2 * b0.y;
            acc.z += w1 * a1.x + w2 * b1.x;
            acc.w += w1 * a1.y + w2 * b1.y;
        }
        __syncwarp();
    }

#pragma unroll
    for (int off = 8; off <= 16; off <<= 1) {
        acc.x += __shfl_xor_sync(0xffffffffu, acc.x, off);
        acc.y += __shfl_xor_sync(0xffffffffu, acc.y, off);
        acc.z += __shfl_xor_sync(0xffffffffu, acc.z, off);
        acc.w += __shfl_xor_sync(0xffffffffu, acc.w, off);
    }
#pragma unroll
    for (int off = 16; off; off >>= 1)
        S += __shfl_xor_sync(0xffffffffu, S, off);

    if (lane < 8) {
        float4 r = make_float4(0.f, 0.f, 0.f, 0.f);
        if (end > beg) {
            float inv = 1.f / S;
            r.x = acc.x * inv; r.y = acc.y * inv;
            r.z = acc.z * inv; r.w = acc.w * inv;
        }
        *(float4*)&out[(size_t)n * F_OUT + lane * 4] = r;
    }
}

// ---------------- launch ----------------
extern "C" void kernel_launch(void* const* d_in, const int* in_sizes, int n_in,
                              void* d_out, int out_size) {
    const float* h   = (const float*)d_in[0];
    const float* W1  = (const float*)d_in[1];
    const float* a1s = (const float*)d_in[2];
    const float* a1d = (const float*)d_in[3];
    const float* W2  = (const float*)d_in[4];
    const float* a2s = (const float*)d_in[5];
    const float* a2d = (const float*)d_in[6];
    const int*   src = (const int*)d_in[7];
    const int*   dst = (const int*)d_in[8];
    float* out = (float*)d_out;

    void *z1p, *h1p, *z2p, *es1p, *ed1p, *es2p, *ed2p, *degp;
    cudaGetSymbolAddress(&z1p, g_z1);
    cudaGetSymbolAddress(&h1p, g_h1);
    cudaGetSymbolAddress(&z2p, g_z2);
    cudaGetSymbolAddress(&es1p, g_es1);
    cudaGetSymbolAddress(&ed1p, g_ed1);
    cudaGetSymbolAddress(&es2p, g_es2);
    cudaGetSymbolAddress(&ed2p, g_ed2);
    cudaGetSymbolAddress(&degp, g_deg);

    static cudaStream_t s1 = nullptr;
    static cudaEvent_t ev0 = nullptr, ev1 = nullptr;
    if (!s1) {
        cudaStreamCreate(&s1);
        cudaEventCreateWithFlags(&ev0, cudaEventDisableTiming);
        cudaEventCreateWithFlags(&ev1, cudaEventDisableTiming);
    }

    const int nb_e = (N_EDGES + 255) / 256;   // 3125
    const int nb_g = (N_NODES + 127) / 128;   // 391
    const int nb_w = (N_NODES + 7) / 8;       // 6250

    // fork: GEMM1 on s1 || CSR chain on main
    cudaEventRecord(ev0, 0);
    cudaStreamWaitEvent(s1, ev0, 0);
    k_gemm_tc<128, 8, 2, 8, 2, __half><<<nb_g, 256, 0, s1>>>(
        h, W1, (__half*)z1p, a1s, a1d, (float*)es1p, (float*)ed1p, N_NODES);
    cudaEventRecord(ev1, s1);

    cudaMemsetAsync(degp, 0, N_NODES * sizeof(int));
    k_hist<<<nb_e, 256>>>(dst);
    k_scan1<<<SCAN_NTILES, SCAN_TPB>>>();
    k_scan2<<<SCAN_NTILES, SCAN_TPB>>>();
    k_scatter<<<nb_e, 256>>>(src, dst);

    cudaStreamWaitEvent(0, ev1, 0);
    k_agg1<<<nb_w, 256>>>();
    k_gemm_tc<32, 4, 1, 1, 4, __half><<<nb_g, 128>>>(
        (const float*)h1p, W2, (__half*)z2p, a2s, a2d, (float*)es2p, (float*)ed2p, N_NODES);
    k_agg2<<<nb_w, 256>>>(out);
}

// round 11
// speedup vs baseline: 1.0228x; 1.0228x over previous
#include <cuda_runtime.h>
#include <cuda_bf16.h>
#include <cuda_fp16.h>
#include <cstdint>

#define N_NODES 50000
#define N_EDGES 800000
#define F_IN    128
#define HDIM    128
#define N_HEADS 8
#define HID     16
#define F_OUT   32
#define NEG_SLOPE 0.2f

// ---------------- device scratch ----------------
__device__ __half g_z1[N_NODES * HDIM];
__device__ float  g_es1[N_NODES * N_HEADS];
__device__ float  g_ed1[N_NODES * N_HEADS];
__device__ float  g_h1[N_NODES * HDIM];
__device__ __half g_z2[N_NODES * F_OUT];
__device__ float  g_es2[N_NODES];
__device__ float  g_ed2[N_NODES];
__device__ int    g_deg[N_NODES];        // zero at entry; scan1 re-zeros after reading
__device__ int    g_rowptr[N_NODES + 1];
__device__ int    g_cursor[N_NODES];
__device__ int    g_csrsrc[N_EDGES];
__device__ int    g_bsum[64];

// ---------------- CSR build ----------------
// 4 edges per thread, int4 loads, batched atomics for MLP
__global__ void k_hist4(const int* __restrict__ dst) {
    int e0 = (blockIdx.x * 256 + threadIdx.x) * 4;
    if (e0 + 3 < N_EDGES) {
        int4 d = *(const int4*)&dst[e0];
        atomicAdd(&g_deg[d.x], 1);
        atomicAdd(&g_deg[d.y], 1);
        atomicAdd(&g_deg[d.z], 1);
        atomicAdd(&g_deg[d.w], 1);
    } else {
        for (int e = e0; e < N_EDGES; e++) atomicAdd(&g_deg[dst[e]], 1);
    }
}

#define SCAN_TPB 256
#define SCAN_ITEMS 8
#define SCAN_TILE 2048
#define SCAN_NTILES ((N_NODES + SCAN_TILE - 1) / SCAN_TILE)   // 25

__global__ void __launch_bounds__(SCAN_TPB) k_scan1() {
    __shared__ int warpsum[8];
    const int t = threadIdx.x;
    const int lane = t & 31, wid = t >> 5;
    const int base = blockIdx.x * SCAN_TILE + t * SCAN_ITEMS;
    int v[SCAN_ITEMS];
    int s = 0;
#pragma unroll
    for (int i = 0; i < SCAN_ITEMS; i++) {
        int idx = base + i;
        v[i] = (idx < N_NODES) ? g_deg[idx] : 0;
        s += v[i];
    }
    // deg is dead after this read: re-zero for next replay (replaces memset)
#pragma unroll
    for (int i = 0; i < SCAN_ITEMS; i++) {
        int idx = base + i;
        if (idx < N_NODES) g_deg[idx] = 0;
    }
    int ps = s;
#pragma unroll
    for (int off = 1; off < 32; off <<= 1) {
        int nv = __shfl_up_sync(0xffffffffu, ps, off);
        if (lane >= off) ps += nv;
    }
    if (lane == 31) warpsum[wid] = ps;
    __syncthreads();
    if (wid == 0) {
        int ws = (lane < 8) ? warpsum[lane] : 0;
#pragma unroll
        for (int off = 1; off < 8; off <<= 1) {
            int nv = __shfl_up_sync(0xffffffffu, ws, off);
            if (lane >= off) ws += nv;
        }
        if (lane < 8) warpsum[lane] = ws;
    }
    __syncthreads();
    int excl = ps - s + (wid ? warpsum[wid - 1] : 0);
    int run = excl;
#pragma unroll
    for (int i = 0; i < SCAN_ITEMS; i++) {
        int idx = base + i;
        if (idx < N_NODES) g_rowptr[idx] = run;
        run += v[i];
    }
    if (t == SCAN_TPB - 1) g_bsum[blockIdx.x] = run;
}

__global__ void __launch_bounds__(SCAN_TPB) k_scan2() {
    const int t = threadIdx.x;
    const int lane = t & 31;
    const int b = blockIdx.x;
    int v = (lane < b) ? g_bsum[lane] : 0;
#pragma unroll
    for (int off = 16; off; off >>= 1) v += __shfl_xor_sync(0xffffffffu, v, off);
    const int offn = v;
    const int base = b * SCAN_TILE + t * SCAN_ITEMS;
#pragma unroll
    for (int i = 0; i < SCAN_ITEMS; i++) {
        int idx = base + i;
        if (idx < N_NODES) {
            int r = g_rowptr[idx] + offn;
            g_rowptr[idx] = r;
            g_cursor[idx] = r;
        }
    }
    if (b == 0 && t == 0) g_rowptr[N_NODES] = N_EDGES;
}

// 4 edges per thread, int4 loads
__global__ void k_scatter4(const int* __restrict__ src, const int* __restrict__ dst) {
    int e0 = (blockIdx.x * 256 + threadIdx.x) * 4;
    if (e0 + 3 < N_EDGES) {
        int4 d = *(const int4*)&dst[e0];
        int4 s = *(const int4*)&src[e0];
        int p0 = atomicAdd(&g_cursor[d.x], 1);
        int p1 = atomicAdd(&g_cursor[d.y], 1);
        int p2 = atomicAdd(&g_cursor[d.z], 1);
        int p3 = atomicAdd(&g_cursor[d.w], 1);
        g_csrsrc[p0] = s.x;
        g_csrsrc[p1] = s.y;
        g_csrsrc[p2] = s.z;
        g_csrsrc[p3] = s.w;
    } else {
        for (int e = e0; e < N_EDGES; e++) {
            int p = atomicAdd(&g_cursor[dst[e]], 1);
            g_csrsrc[p] = src[e];
        }
    }
}

// ---------------- bf16 split-MMA GEMM + fused attention-dot epilogue ----------------
__device__ __forceinline__ void ldsm_x4(uint32_t& r0, uint32_t& r1, uint32_t& r2, uint32_t& r3,
                                        uint32_t addr) {
    asm volatile("ldmatrix.sync.aligned.m8n8.x4.shared.b16 {%0,%1,%2,%3}, [%4];"
                 : "=r"(r0), "=r"(r1), "=r"(r2), "=r"(r3) : "r"(addr));
}
__device__ __forceinline__ void ldsm_x4t(uint32_t& r0, uint32_t& r1, uint32_t& r2, uint32_t& r3,
                                         uint32_t addr) {
    asm volatile("ldmatrix.sync.aligned.m8n8.x4.trans.shared.b16 {%0,%1,%2,%3}, [%4];"
                 : "=r"(r0), "=r"(r1), "=r"(r2), "=r"(r3) : "r"(addr));
}
__device__ __forceinline__ void mma_bf16(float* c, const uint32_t* a, uint32_t b0, uint32_t b1) {
    asm volatile(
        "mma.sync.aligned.m16n8k16.row.col.f32.bf16.bf16.f32 "
        "{%0,%1,%2,%3}, {%4,%5,%6,%7}, {%8,%9}, {%0,%1,%2,%3};"
        : "+f"(c[0]), "+f"(c[1]), "+f"(c[2]), "+f"(c[3])
        : "r"(a[0]), "r"(a[1]), "r"(a[2]), "r"(a[3]), "r"(b0), "r"(b1));
}
__device__ __forceinline__ void cvt_hilo(float x, __nv_bfloat16& h, __nv_bfloat16& l) {
    h = __float2bfloat16(x);
    l = __float2bfloat16(x - __bfloat162float(h));
}

template <int BN, int NWARP, int WC, int NH, int MINB, typename CT>
__global__ void __launch_bounds__(NWARP * 32, MINB)
k_gemm_tc(const float* __restrict__ A, const float* __restrict__ B,
          CT* __restrict__ C,
          const float* __restrict__ avs, const float* __restrict__ avd,
          float* __restrict__ esp, float* __restrict__ edp, int M) {
    constexpr int BM = 128, K = 128, BK = 16, NK = K / BK;
    constexpr int NT = NWARP * 32;
    constexpr int SAS = 24;
    constexpr int BNS = BN + 8;
    constexpr int WR = NWARP / WC;
    constexpr int WTN = BN / WC;
    constexpr int NTW = WTN / 8;
    constexpr int HD = BN / NH;
    constexpr int HWN = WTN / HD;
    constexpr int LA4 = (BM * BK / 4) / NT;
    constexpr int LB4 = (BK * BN / 4) / NT;

    __shared__ __nv_bfloat16 sAh[2][BM][SAS];
    __shared__ __nv_bfloat16 sAl[2][BM][SAS];
    __shared__ __nv_bfloat16 sBh[2][BK][BNS];
    __shared__ __nv_bfloat16 sBl[2][BK][BNS];

    const int tid = threadIdx.x;
    const int lane = tid & 31;
    const int wid = tid >> 5;
    const int row0 = blockIdx.x * BM;
    const int tmW = (wid / WC) * (BM / WR);
    const int tnW = (wid % WC) * WTN;

    float4 ra[LA4], rb[LB4];

    auto ldg_tile = [&](int kt) {
        const int k0 = kt * BK;
#pragma unroll
        for (int l = 0; l < LA4; l++) {
            int idx = tid + l * NT;
            int r = idx >> 2, kq = idx & 3;
            int row = row0 + r;
            ra[l] = (row < M) ? *(const float4*)&A[(size_t)row * K + k0 + kq * 4]
                              : make_float4(0.f, 0.f, 0.f, 0.f);
        }
#pragma unroll
        for (int l = 0; l < LB4; l++) {
            int idx = tid + l * NT;
            int k = idx / (BN / 4), nq = idx % (BN / 4);
            rb[l] = *(const float4*)&B[(size_t)(k0 + k) * BN + nq * 4];
        }
    };
    auto sts_tile = [&](int buf) {
#pragma unroll
        for (int l = 0; l < LA4; l++) {
            int idx = tid + l * NT;
            int r = idx >> 2, kq = idx & 3;
            __nv_bfloat16 h0, h1, h2, h3, l0, l1, l2, l3;
            cvt_hilo(ra[l].x, h0, l0); cvt_hilo(ra[l].y, h1, l1);
            cvt_hilo(ra[l].z, h2, l2); cvt_hilo(ra[l].w, h3, l3);
            *(__nv_bfloat162*)&sAh[buf][r][kq * 4]     = __nv_bfloat162(h0, h1);
            *(__nv_bfloat162*)&sAh[buf][r][kq * 4 + 2] = __nv_bfloat162(h2, h3);
            *(__nv_bfloat162*)&sAl[buf][r][kq * 4]     = __nv_bfloat162(l0, l1);
            *(__nv_bfloat162*)&sAl[buf][r][kq * 4 + 2] = __nv_bfloat162(l2, l3);
        }
#pragma unroll
        for (int l = 0; l < LB4; l++) {
            int idx = tid + l * NT;
            int k = idx / (BN / 4), nq = idx % (BN / 4);
            __nv_bfloat16 h0, h1, h2, h3, l0, l1, l2, l3;
            cvt_hilo(rb[l].x, h0, l0); cvt_hilo(rb[l].y, h1, l1);
            cvt_hilo(rb[l].z, h2, l2); cvt_hilo(rb[l].w, h3, l3);
            *(__nv_bfloat162*)&sBh[buf][k][nq * 4]     = __nv_bfloat162(h0, h1);
            *(__nv_bfloat162*)&sBh[buf][k][nq * 4 + 2] = __nv_bfloat162(h2, h3);
            *(__nv_bfloat162*)&sBl[buf][k][nq * 4]     = __nv_bfloat162(l0, l1);
            *(__nv_bfloat162*)&sBl[buf][k][nq * 4 + 2] = __nv_bfloat162(l2, l3);
        }
    };

    float acc[2][NTW][4];
#pragma unroll
    for (int i = 0; i < 2; i++)
#pragma unroll
        for (int j = 0; j < NTW; j++)
#pragma unroll
            for (int q = 0; q < 4; q++) acc[i][j][q] = 0.f;

    ldg_tile(0);
    sts_tile(0);
    int cur = 0;

    const int aRow = (lane & 7) + ((lane & 8) ? 8 : 0);
    const int aCol = (lane & 16) ? 8 : 0;
    const int bK = aRow;
    const int bN = aCol;

    for (int kt = 0; kt < NK; kt++) {
        if (kt + 1 < NK) ldg_tile(kt + 1);
        __syncthreads();

        uint32_t ah[2][4], al[2][4];
#pragma unroll
        for (int mt = 0; mt < 2; mt++) {
            int r = tmW + mt * 16 + aRow;
            uint32_t addrh = (uint32_t)__cvta_generic_to_shared(&sAh[cur][r][aCol]);
            uint32_t addrl = (uint32_t)__cvta_generic_to_shared(&sAl[cur][r][aCol]);
            ldsm_x4(ah[mt][0], ah[mt][1], ah[mt][2], ah[mt][3], addrh);
            ldsm_x4(al[mt][0], al[mt][1], al[mt][2], al[mt][3], addrl);
        }
#pragma unroll
        for (int p = 0; p < NTW / 2; p++) {
            int n = tnW + p * 16 + bN;
            uint32_t addrh = (uint32_t)__cvta_generic_to_shared(&sBh[cur][bK][n]);
            uint32_t addrl = (uint32_t)__cvta_generic_to_shared(&sBl[cur][bK][n]);
            uint32_t bh0, bh1, bh2, bh3, bl0, bl1, bl2, bl3;
            ldsm_x4t(bh0, bh1, bh2, bh3, addrh);
            ldsm_x4t(bl0, bl1, bl2, bl3, addrl);
#pragma unroll
            for (int mt = 0; mt < 2; mt++) {
                mma_bf16(acc[mt][2 * p],     ah[mt], bh0, bh1);
                mma_bf16(acc[mt][2 * p],     ah[mt], bl0, bl1);
                mma_bf16(acc[mt][2 * p],     al[mt], bh0, bh1);
                mma_bf16(acc[mt][2 * p + 1], ah[mt], bh2, bh3);
                mma_bf16(acc[mt][2 * p + 1], ah[mt], bl2, bl3);
                mma_bf16(acc[mt][2 * p + 1], al[mt], bh2, bh3);
            }
        }
        if (kt + 1 < NK) sts_tile(cur ^ 1);
        cur ^= 1;
    }

    const int cRow = lane >> 2;
    const int cCol = (lane & 3) * 2;
#pragma unroll
    for (int mt = 0; mt < 2; mt++)
#pragma unroll
        for (int nt = 0; nt < NTW; nt++) {
            int col = tnW + nt * 8 + cCol;
            int r1 = row0 + tmW + mt * 16 + cRow;
            int r2 = r1 + 8;
            if constexpr (sizeof(CT) == 2) {
                if (r1 < M) *(__half2*)&C[(size_t)r1 * BN + col] =
                    __floats2half2_rn(acc[mt][nt][0], acc[mt][nt][1]);
                if (r2 < M) *(__half2*)&C[(size_t)r2 * BN + col] =
                    __floats2half2_rn(acc[mt][nt][2], acc[mt][nt][3]);
            } else {
                if (r1 < M) *(float2*)&C[(size_t)r1 * BN + col] = make_float2(acc[mt][nt][0], acc[mt][nt][1]);
                if (r2 < M) *(float2*)&C[(size_t)r2 * BN + col] = make_float2(acc[mt][nt][2], acc[mt][nt][3]);
            }
        }

    float pes[2][2][HWN], ped[2][2][HWN];
#pragma unroll
    for (int mt = 0; mt < 2; mt++)
#pragma unroll
        for (int pr = 0; pr < 2; pr++)
#pragma unroll
            for (int hw = 0; hw < HWN; hw++) { pes[mt][pr][hw] = 0.f; ped[mt][pr][hw] = 0.f; }
#pragma unroll
    for (int mt = 0; mt < 2; mt++)
#pragma unroll
        for (int nt = 0; nt < NTW; nt++) {
            int hw = (nt * 8) / HD;
            int c = tnW + nt * 8 + cCol;
            float s0 = avs[c], s1 = avs[c + 1];
            float d0 = avd[c], d1 = avd[c + 1];
            pes[mt][0][hw] += acc[mt][nt][0] * s0 + acc[mt][nt][1] * s1;
            pes[mt][1][hw] += acc[mt][nt][2] * s0 + acc[mt][nt][3] * s1;
            ped[mt][0][hw] += acc[mt][nt][0] * d0 + acc[mt][nt][1] * d1;
            ped[mt][1][hw] += acc[mt][nt][2] * d0 + acc[mt][nt][3] * d1;
        }
#pragma unroll
    for (int mt = 0; mt < 2; mt++)
#pragma unroll
        for (int pr = 0; pr < 2; pr++)
#pragma unroll
            for (int hw = 0; hw < HWN; hw++) {
#pragma unroll
                for (int off = 1; off <= 2; off <<= 1) {
                    pes[mt][pr][hw] += __shfl_xor_sync(0xffffffffu, pes[mt][pr][hw], off);
                    ped[mt][pr][hw] += __shfl_xor_sync(0xffffffffu, ped[mt][pr][hw], off);
                }
            }
    if ((lane & 3) == 0) {
#pragma unroll
        for (int mt = 0; mt < 2; mt++)
#pragma unroll
            for (int pr = 0; pr < 2; pr++) {
                int row = row0 + tmW + mt * 16 + pr * 8 + cRow;
                if (row < M) {
#pragma unroll
                    for (int hw = 0; hw < HWN; hw++) {
                        int hg = tnW / HD + hw;
                        esp[(size_t)row * NH + hg] = pes[mt][pr][hw];
                        edp[(size_t)row * NH + hg] = ped[mt][pr][hw];
                    }
                }
            }
    }
}

// ---------------- layer1 aggregation (warp/node, unroll-8 gather) ----------------
__global__ void __launch_bounds__(256) k_agg1() {
    __shared__ int   ss[8][32];
    __shared__ float ws[8][8][33];
    const int w = threadIdx.x >> 5;
    const int lane = threadIdx.x & 31;
    const int n = blockIdx.x * 8 + w;
    if (n >= N_NODES) return;
    const int beg = g_rowptr[n], end = g_rowptr[n + 1];
    const int head = lane >> 2;

    float ed[8];
    {
        float4 lo = *(const float4*)&g_ed1[n * 8];
        float4 hi = *(const float4*)&g_ed1[n * 8 + 4];
        ed[0] = lo.x; ed[1] = lo.y; ed[2] = lo.z; ed[3] = lo.w;
        ed[4] = hi.x; ed[5] = hi.y; ed[6] = hi.z; ed[7] = hi.w;
    }

    float4 acc = make_float4(0.f, 0.f, 0.f, 0.f);
    float ssum[8];
#pragma unroll
    for (int h = 0; h < 8; h++) ssum[h] = 0.f;

    for (int base = beg; base < end; base += 32) {
        const int cnt = min(32, end - base);
        float wv[8];
        int sv = 0;
        if (lane < cnt) {
            sv = g_csrsrc[base + lane];
            float4 lo = *(const float4*)&g_es1[sv * 8];
            float4 hi = *(const float4*)&g_es1[sv * 8 + 4];
            float es[8] = {lo.x, lo.y, lo.z, lo.w, hi.x, hi.y, hi.z, hi.w};
#pragma unroll
            for (int h = 0; h < 8; h++) {
                float t = es[h] + ed[h];
                t = (t >= 0.f) ? t : NEG_SLOPE * t;
                wv[h] = __expf(t);
                ssum[h] += wv[h];
            }
        } else {
#pragma unroll
            for (int h = 0; h < 8; h++) wv[h] = 0.f;
        }
        ss[w][lane] = sv;
#pragma unroll
        for (int h = 0; h < 8; h++) ws[w][h][lane] = wv[h];
        __syncwarp();

        for (int j = 0; j < cnt; j += 8) {
#pragma unroll
            for (int u = 0; u < 8; u++) {
                int s = ss[w][j + u];
                float wt = ws[w][head][j + u];
                uint2 raw = *(const uint2*)&g_z1[(size_t)s * HDIM + lane * 4];
                float2 f0 = __half22float2(*(__half2*)&raw.x);
                float2 f1 = __half22float2(*(__half2*)&raw.y);
                acc.x += wt * f0.x; acc.y += wt * f0.y;
                acc.z += wt * f1.x; acc.w += wt * f1.y;
            }
        }
        __syncwarp();
    }

#pragma unroll
    for (int h = 0; h < 8; h++)
#pragma unroll
        for (int off = 16; off; off >>= 1)
            ssum[h] += __shfl_xor_sync(0xffffffffu, ssum[h], off);

    float4 r = make_float4(0.f, 0.f, 0.f, 0.f);
    if (end > beg) {
        float inv = 1.f / ssum[head];
        r.x = acc.x * inv; r.y = acc.y * inv;
        r.z = acc.z * inv; r.w = acc.w * inv;
    }
    r.x = (r.x > 0.f) ? r.x : expm1f(r.x);
    r.y = (r.y > 0.f) ? r.y : expm1f(r.y);
    r.z = (r.z > 0.f) ? r.z : expm1f(r.z);
    r.w = (r.w > 0.f) ? r.w : expm1f(r.w);
    *(float4*)&g_h1[(size_t)n * HDIM + lane * 4] = r;
}

// ---------------- layer2 aggregation (warp/node, 8 edges in flight) ----------------
__global__ void __launch_bounds__(256) k_agg2(float* __restrict__ out) {
    __shared__ int   ss[8][32];
    __shared__ float ws[8][32];
    const int w = threadIdx.x >> 5;
    const int lane = threadIdx.x & 31;
    const int n = blockIdx.x * 8 + w;
    if (n >= N_NODES) return;
    const int beg = g_rowptr[n], end = g_rowptr[n + 1];
    const float ed = g_ed2[n];
    const int eslot = lane >> 3;
    const int cg = lane & 7;
    float4 acc = make_float4(0.f, 0.f, 0.f, 0.f);
    float S = 0.f;

    for (int base = beg; base < end; base += 32) {
        const int cnt = min(32, end - base);
        float wv = 0.f;
        int sv = 0;
        if (lane < cnt) {
            sv = g_csrsrc[base + lane];
            float t = g_es2[sv] + ed;
            t = (t >= 0.f) ? t : NEG_SLOPE * t;
            wv = __expf(t);
            S += wv;
        }
        ss[w][lane] = sv;
        ws[w][lane] = wv;
        __syncwarp();

        for (int j = 0; j < cnt; j += 8) {
            int j1 = j + eslot;
            int j2 = j + 4 + eslot;
            int s1v = ss[w][j1];
            int s2v = ss[w][j2];
            float w1 = ws[w][j1];
            float w2 = ws[w][j2];
            uint2 raw1 = *(const uint2*)&g_z2[(size_t)s1v * F_OUT + cg * 4];
            uint2 raw2 = *(const uint2*)&g_z2[(size_t)s2v * F_OUT + cg * 4];
            float2 a0 = __half22float2(*(__half2*)&raw1.x);
            float2 a1 = __half22float2(*(__half2*)&raw1.y);
            float2 b0 = __half22float2(*(__half2*)&raw2.x);
            float2 b1 = __half22float2(*(__half2*)&raw2.y);
            acc.x += w1 * a0.x + w2 * b0.x;
            acc.y += w1 * a0.y + w2 * b0.y;
            acc.z += w1 * a1.x + w2 * b1.x;
            acc.w += w1 * a1.y + w2 * b1.y;
        }
        __syncwarp();
    }

#pragma unroll
    for (int off = 8; off <= 16; off <<= 1) {
        acc.x += __shfl_xor_sync(0xffffffffu, acc.x, off);
        acc.y += __shfl_xor_sync(0xffffffffu, acc.y, off);
        acc.z += __shfl_xor_sync(0xffffffffu, acc.z, off);
        acc.w += __shfl_xor_sync(0xffffffffu, acc.w, off);
    }
#pragma unroll
    for (int off = 16; off; off >>= 1)
        S += __shfl_xor_sync(0xffffffffu, S, off);

    if (lane < 8) {
        float4 r = make_float4(0.f, 0.f, 0.f, 0.f);
        if (end > beg) {
            float inv = 1.f / S;
            r.x = acc.x * inv; r.y = acc.y * inv;
            r.z = acc.z * inv; r.w = acc.w * inv;
        }
        *(float4*)&out[(size_t)n * F_OUT + lane * 4] = r;
    }
}

// ---------------- launch ----------------
extern "C" void kernel_launch(void* const* d_in, const int* in_sizes, int n_in,
                              void* d_out, int out_size) {
    const float* h   = (const float*)d_in[0];
    const float* W1  = (const float*)d_in[1];
    const float* a1s = (const float*)d_in[2];
    const float* a1d = (const float*)d_in[3];
    const float* W2  = (const float*)d_in[4];
    const float* a2s = (const float*)d_in[5];
    const float* a2d = (const float*)d_in[6];
    const int*   src = (const int*)d_in[7];
    const int*   dst = (const int*)d_in[8];
    float* out = (float*)d_out;

    void *z1p, *h1p, *z2p, *es1p, *ed1p, *es2p, *ed2p;
    cudaGetSymbolAddress(&z1p, g_z1);
    cudaGetSymbolAddress(&h1p, g_h1);
    cudaGetSymbolAddress(&z2p, g_z2);
    cudaGetSymbolAddress(&es1p, g_es1);
    cudaGetSymbolAddress(&ed1p, g_ed1);
    cudaGetSymbolAddress(&es2p, g_es2);
    cudaGetSymbolAddress(&ed2p, g_ed2);

    static cudaStream_t s1 = nullptr;
    static cudaEvent_t ev0 = nullptr, ev1 = nullptr;
    if (!s1) {
        cudaStreamCreate(&s1);
        cudaEventCreateWithFlags(&ev0, cudaEventDisableTiming);
        cudaEventCreateWithFlags(&ev1, cudaEventDisableTiming);
    }

    const int nb_e4 = (N_EDGES / 4 + 255) / 256;   // 782
    const int nb_g = (N_NODES + 127) / 128;        // 391
    const int nb_w = (N_NODES + 7) / 8;            // 6250

    // fork: GEMM1 on s1 || CSR chain on main
    cudaEventRecord(ev0, 0);
    cudaStreamWaitEvent(s1, ev0, 0);
    k_gemm_tc<128, 8, 2, 8, 2, __half><<<nb_g, 256, 0, s1>>>(
        h, W1, (__half*)z1p, a1s, a1d, (float*)es1p, (float*)ed1p, N_NODES);
    cudaEventRecord(ev1, s1);

    k_hist4<<<nb_e4, 256>>>(dst);
    k_scan1<<<SCAN_NTILES, SCAN_TPB>>>();
    k_scan2<<<SCAN_NTILES, SCAN_TPB>>>();
    k_scatter4<<<nb_e4, 256>>>(src, dst);

    cudaStreamWaitEvent(0, ev1, 0);
    k_agg1<<<nb_w, 256>>>();
    k_gemm_tc<32, 4, 1, 1, 4, __half><<<nb_g, 128>>>(
        (const float*)h1p, W2, (__half*)z2p, a2s, a2d, (float*)es2p, (float*)ed2p, N_NODES);
    k_agg2<<<nb_w, 256>>>(out);
}